// round 15
// baseline (speedup 1.0000x reference)
#include <cuda_runtime.h>
#include <cstdint>

#define Bn   128
#define Tn   50
#define MI   32
#define En   128
#define Dn   144
#define G3   432
#define KD   144
#define KH   72           // GEMM k-slab
#define KP2  76           // padded slab stride (floats)
#define GRT  144          // GRU threads: rows j, j+144, j+288 per thread
#define CR2  64           // register k-pairs per row (128 k-cols)
#define TW2  4            // tail ulonglong2 per row (16 k-cols)

typedef unsigned long long ull;

__device__ float g_seq [Bn*Tn*Dn];
__device__ float g_gi  [Bn*Tn*G3];
__device__ float g_hseq[Bn*Tn*Dn];

// ---- f32x2 helpers ---------------------------------------------------------
__device__ __forceinline__ void fma2(ull& d, ull a, ull b) {
    asm("fma.rn.f32x2 %0, %1, %2, %0;" : "+l"(d) : "l"(a), "l"(b));
}
__device__ __forceinline__ void add2(ull& d, ull a) {
    asm("add.rn.f32x2 %0, %0, %1;" : "+l"(d) : "l"(a));
}
__device__ __forceinline__ float hsum2(ull v) {
    float lo, hi;
    asm("mov.b64 {%0,%1}, %2;" : "=f"(lo), "=f"(hi) : "l"(v));
    return lo + hi;
}
__device__ __forceinline__ ull pack2(float lo, float hi) {
    ull v;
    asm("mov.b64 %0, {%1,%2};" : "=l"(v) : "f"(lo), "f"(hi));
    return v;
}

// ---------------------------------------------------------------------------
__global__ void noop_kernel() {}

// ---------------------------------------------------------------------------
// 1) basket embedding (1 warp does the 128-wide mean pool, float4 gathers)
// ---------------------------------------------------------------------------
__global__ void __launch_bounds__(64)
embed_kernel(const int* __restrict__ x,
             const float* __restrict__ encode_w,
             const float* __restrict__ wchange_w) {
    int bt = blockIdx.x;
    const int* xr = x + (size_t)bt * (MI + 1);
    __shared__ int s_items[MI];
    __shared__ int s_flag;
    int tid = threadIdx.x;
    if (tid < MI) s_items[tid] = xr[tid];
    if (tid == MI) s_flag = xr[MI];
    __syncthreads();

    if (tid < 32) {
        float4 acc = make_float4(0.f, 0.f, 0.f, 0.f);
        int cnt = 0;
        #pragma unroll
        for (int i = 0; i < MI; i++) {
            int it = s_items[i];
            if (it != 0) {
                cnt++;
                float4 v = *(const float4*)(encode_w + (size_t)it * En + 4 * tid);
                acc.x += v.x; acc.y += v.y; acc.z += v.z; acc.w += v.w;
            }
        }
        float inv = 1.f / (float)(cnt > 0 ? cnt : 1);
        acc.x *= inv; acc.y *= inv; acc.z *= inv; acc.w *= inv;
        *(float4*)(g_seq + (size_t)bt * Dn + 4 * tid) = acc;
    } else if (tid < 48) {
        g_seq[(size_t)bt * Dn + En + (tid - 32)] = wchange_w[s_flag * 16 + (tid - 32)];
    }
}

// ---------------------------------------------------------------------------
// 2a) gi GEMM: C[M,432] = A[M,144]*Bm[432,144]^T + bias (64x64, 128 thr)
// ---------------------------------------------------------------------------
__global__ void __launch_bounds__(128)
gemm_tn(const float* __restrict__ A, const float* __restrict__ Bm,
        const float* __restrict__ bias, float* __restrict__ C, int N) {
    extern __shared__ float sm[];
    float* Ast = sm;              // [64][KP2]
    float* Bst = sm + 64 * KP2;   // [64][KP2]

    int tid = threadIdx.x;
    int m0 = blockIdx.y * 64, n0 = blockIdx.x * 64;
    int tx = tid & 15, ty = tid >> 4;

    ull acc[8][4];
    #pragma unroll
    for (int i = 0; i < 8; i++)
        #pragma unroll
        for (int j = 0; j < 4; j++) acc[i][j] = 0ull;

    for (int ks = 0; ks < 2; ks++) {
        int k0 = ks * KH;
        #pragma unroll
        for (int p = 0; p < 9; p++) {
            int idx = tid + p * 128;
            int r = idx / 18, c = idx - 18 * r;
            *(float4*)(Ast + r * KP2 + 4 * c) =
                *(const float4*)(A + (size_t)(m0 + r) * KD + k0 + 4 * c);
        }
        #pragma unroll
        for (int p = 0; p < 9; p++) {
            int idx = tid + p * 128;
            int r = idx / 18, c = idx - 18 * r;
            float4 v = make_float4(0.f, 0.f, 0.f, 0.f);
            if (n0 + r < N)
                v = *(const float4*)(Bm + (size_t)(n0 + r) * KD + k0 + 4 * c);
            *(float4*)(Bst + r * KP2 + 4 * c) = v;
        }
        __syncthreads();

        const float* aBase = Ast + (8 * ty) * KP2;
        const ulonglong2* bP[4];
        #pragma unroll
        for (int j = 0; j < 4; j++)
            bP[j] = (const ulonglong2*)(Bst + (tx + 16 * j) * KP2);

        #pragma unroll 6
        for (int kq = 0; kq < 18; kq++) {
            ulonglong2 b[4];
            #pragma unroll
            for (int j = 0; j < 4; j++) b[j] = bP[j][kq];
            #pragma unroll
            for (int i = 0; i < 8; i++) {
                ulonglong2 a = ((const ulonglong2*)(aBase + i * KP2))[kq];
                #pragma unroll
                for (int j = 0; j < 4; j++) {
                    fma2(acc[i][j], a.x, b[j].x);
                    fma2(acc[i][j], a.y, b[j].y);
                }
            }
        }
        __syncthreads();
    }

    #pragma unroll
    for (int j = 0; j < 4; j++) {
        int n = n0 + tx + 16 * j;
        if (n < N) {
            float bv = bias[n];
            #pragma unroll
            for (int i = 0; i < 8; i++) {
                int m = m0 + 8 * ty + i;
                C[(size_t)m * N + n] = hsum2(acc[i][j]) + bv;
            }
        }
    }
}

// ---------------------------------------------------------------------------
// 2b) fc GEMM: C[M,128] = A[M,144]*Bm[128,144]^T + bias
//     64m x 128n tile, 256 threads, 4m x 8n micro-tile, grid = M/64 (1 wave)
// ---------------------------------------------------------------------------
__global__ void __launch_bounds__(256)
gemm_fc(const float* __restrict__ A, const float* __restrict__ Bm,
        const float* __restrict__ bias, float* __restrict__ C) {
    extern __shared__ float sm[];
    float* Ast = sm;               // [64][KP2]
    float* Bst = sm + 64 * KP2;    // [128][KP2]

    int tid = threadIdx.x;
    int m0 = blockIdx.x * 64;
    int tx = tid & 15, ty = tid >> 4;

    ull acc[4][8];
    #pragma unroll
    for (int i = 0; i < 4; i++)
        #pragma unroll
        for (int j = 0; j < 8; j++) acc[i][j] = 0ull;

    for (int ks = 0; ks < 2; ks++) {
        int k0 = ks * KH;
        #pragma unroll
        for (int p = 0; p < 5; p++) {
            int idx = tid + p * 256;
            if (idx < 1152) {
                int r = idx / 18, c = idx - 18 * r;
                *(float4*)(Ast + r * KP2 + 4 * c) =
                    *(const float4*)(A + (size_t)(m0 + r) * KD + k0 + 4 * c);
            }
        }
        #pragma unroll
        for (int p = 0; p < 9; p++) {
            int idx = tid + p * 256;
            int r = idx / 18, c = idx - 18 * r;
            *(float4*)(Bst + r * KP2 + 4 * c) =
                *(const float4*)(Bm + (size_t)r * KD + k0 + 4 * c);
        }
        __syncthreads();

        const float* aBase = Ast + (4 * ty) * KP2;
        const ulonglong2* bP[8];
        #pragma unroll
        for (int j = 0; j < 8; j++)
            bP[j] = (const ulonglong2*)(Bst + (tx + 16 * j) * KP2);

        #pragma unroll 6
        for (int kq = 0; kq < 18; kq++) {
            ulonglong2 b[8];
            #pragma unroll
            for (int j = 0; j < 8; j++) b[j] = bP[j][kq];
            #pragma unroll
            for (int i = 0; i < 4; i++) {
                ulonglong2 a = ((const ulonglong2*)(aBase + i * KP2))[kq];
                #pragma unroll
                for (int j = 0; j < 8; j++) {
                    fma2(acc[i][j], a.x, b[j].x);
                    fma2(acc[i][j], a.y, b[j].y);
                }
            }
        }
        __syncthreads();
    }

    #pragma unroll
    for (int j = 0; j < 8; j++) {
        int n = tx + 16 * j;
        float bv = bias[n];
        #pragma unroll
        for (int i = 0; i < 4; i++) {
            int m = m0 + 4 * ty + i;
            C[(size_t)m * En + n] = hsum2(acc[i][j]) + bv;
        }
    }
}

// ---------------------------------------------------------------------------
// 3) GRU: one CTA per batch (grid=128), 144 threads. Thread j owns rows
//    j (r), j+144 (z), j+288 (n): the whole gate triple -> epilogue is pure
//    register math, no s_A exchange. h double-buffered -> ONE barrier/step.
//    k<128 weights in regs (3x64 pairs); 16-col tail in smem.
// ---------------------------------------------------------------------------
__global__ void __launch_bounds__(GRT, 1)
gru_kernel(const float* __restrict__ w_hh, const float* __restrict__ b_hh,
           const float* __restrict__ hidden, float* __restrict__ out) {
    __shared__ __align__(16) float s_h[2][Dn];
    __shared__ ulonglong2 s_wtR[TW2 * GRT];
    __shared__ ulonglong2 s_wtZ[TW2 * GRT];
    __shared__ ulonglong2 s_wtN[TW2 * GRT];

    int b = blockIdx.x;
    int j = threadIdx.x;

    const ull* wrR = (const ull*)(w_hh + (size_t)j * KD);
    const ull* wrZ = (const ull*)(w_hh + (size_t)(j + Dn) * KD);
    const ull* wrN = (const ull*)(w_hh + (size_t)(j + 2 * Dn) * KD);

    ull wR[CR2], wZ[CR2], wN[CR2];
    #pragma unroll
    for (int p = 0; p < CR2; p++) wR[p] = wrR[p];
    #pragma unroll
    for (int p = 0; p < CR2; p++) wZ[p] = wrZ[p];
    #pragma unroll
    for (int p = 0; p < CR2; p++) wN[p] = wrN[p];
    #pragma unroll
    for (int p = 0; p < TW2; p++) {
        s_wtR[p * GRT + j] = make_ulonglong2(wrR[CR2 + 2 * p], wrR[CR2 + 2 * p + 1]);
        s_wtZ[p * GRT + j] = make_ulonglong2(wrZ[CR2 + 2 * p], wrZ[CR2 + 2 * p + 1]);
        s_wtN[p * GRT + j] = make_ulonglong2(wrN[CR2 + 2 * p], wrN[CR2 + 2 * p + 1]);
    }

    float biasR = b_hh[j];
    float biasZ = b_hh[j + Dn];
    float biasN = b_hh[j + 2 * Dn];

    float h_prev = hidden[(size_t)b * Dn + j];
    s_h[0][j] = h_prev;
    __syncthreads();

    const float* giB = g_gi + (size_t)b * Tn * G3;
    float* hsB       = g_hseq + (size_t)b * Tn * Dn;

    float gR = giB[j], gZ = giB[j + Dn], gN = giB[j + 2 * Dn];   // t=0 prefetch

    for (int t = 0; t < Tn; t++) {
        const ulonglong2* h2 = (const ulonglong2*)s_h[t & 1];

        ull aR0 = pack2(biasR, 0.f), aR1 = 0ull;
        ull aZ0 = pack2(biasZ, 0.f), aZ1 = 0ull;
        ull aN0 = pack2(biasN, 0.f), aN1 = 0ull;

        #pragma unroll
        for (int q = 0; q < CR2 / 2; q++) {            // k 0..127 (regs)
            ulonglong2 x = h2[q];
            fma2(aR0, wR[2 * q],     x.x);
            fma2(aR1, wR[2 * q + 1], x.y);
            fma2(aZ0, wZ[2 * q],     x.x);
            fma2(aZ1, wZ[2 * q + 1], x.y);
            fma2(aN0, wN[2 * q],     x.x);
            fma2(aN1, wN[2 * q + 1], x.y);
        }
        #pragma unroll
        for (int p = 0; p < TW2; p++) {                // k 128..143 (smem)
            ulonglong2 x  = h2[CR2 / 2 + p];
            ulonglong2 tR = s_wtR[p * GRT + j];
            ulonglong2 tZ = s_wtZ[p * GRT + j];
            ulonglong2 tN = s_wtN[p * GRT + j];
            fma2(aR0, tR.x, x.x);  fma2(aR1, tR.y, x.y);
            fma2(aZ0, tZ.x, x.x);  fma2(aZ1, tZ.y, x.y);
            fma2(aN0, tN.x, x.x);  fma2(aN1, tN.y, x.y);
        }
        add2(aR0, aR1);
        add2(aZ0, aZ1);
        add2(aN0, aN1);
        float AR = hsum2(aR0);
        float AZ = hsum2(aZ0);
        float AN = hsum2(aN0);

        float gRv = gR, gZv = gZ, gNv = gN;
        if (t + 1 < Tn) {
            const float* gnext = giB + (t + 1) * G3;
            gR = gnext[j]; gZ = gnext[j + Dn]; gN = gnext[j + 2 * Dn];
        }

        // epilogue: pure register math
        float r = __fdividef(1.f, 1.f + __expf(-(gRv + AR)));
        float z = __fdividef(1.f, 1.f + __expf(-(gZv + AZ)));
        float e = __expf(-2.f * (gNv + r * AN));
        float n = __fdividef(2.f, 1.f + e) - 1.f;      // tanh
        float hn = (1.f - z) * n + z * h_prev;
        h_prev = hn;

        s_h[(t + 1) & 1][j] = hn;
        hsB[t * Dn + j] = hn;
        __syncthreads();                               // ONE barrier per step
    }

    out[(size_t)Bn * Tn * En + (size_t)b * Dn + j] = h_prev;
}

// ---------------------------------------------------------------------------
extern "C" void kernel_launch(void* const* d_in, const int* in_sizes, int n_in,
                              void* d_out, int out_size) {
    const int*   x        = (const int*)  d_in[0];
    const float* hidden   = (const float*)d_in[2];
    const float* encode_w = (const float*)d_in[3];
    const float* wchange  = (const float*)d_in[4];
    const float* w_ih     = (const float*)d_in[5];
    const float* w_hh     = (const float*)d_in[6];
    const float* b_ih     = (const float*)d_in[7];
    const float* b_hh     = (const float*)d_in[8];
    const float* fc_w     = (const float*)d_in[9];
    const float* fc_b     = (const float*)d_in[10];
    float* out = (float*)d_out;

    float *p_seq, *p_gi, *p_hseq;
    cudaGetSymbolAddress((void**)&p_seq,  g_seq);
    cudaGetSymbolAddress((void**)&p_gi,   g_gi);
    cudaGetSymbolAddress((void**)&p_hseq, g_hseq);

    const int gemm_smem = 2 * 64 * KP2 * 4;                   // 38912 B
    const int fc_smem   = (64 + 128) * KP2 * 4;               // 58368 B
    cudaFuncSetAttribute(gemm_fc, cudaFuncAttributeMaxDynamicSharedMemorySize, fc_smem);

    // 1) embed
    embed_kernel<<<Bn * Tn, 64>>>(x, encode_w, wchange);

    // 2) gi = seq @ w_ih^T + b_ih   (6400 x 432)
    {
        dim3 grid((G3 + 63) / 64, (Bn * Tn) / 64);
        gemm_tn<<<grid, 128, gemm_smem>>>(p_seq, w_ih, b_ih, p_gi, G3);
    }

    // spacer so the ncu capture slot lands on the GRU kernel
    noop_kernel<<<1, 32>>>();

    // 3) GRU recurrence (one CTA per batch row, grid=128)
    gru_kernel<<<Bn, GRT>>>(w_hh, b_hh, hidden, out);

    // 4) dynamic_user = hseq @ fc_w^T + fc_b  (6400 x 128) -> out head
    gemm_fc<<<(Bn * Tn) / 64, 256, fc_smem>>>(p_hseq, fc_w, fc_b, out);
}

// round 16
// speedup vs baseline: 1.8930x; 1.8930x over previous
#include <cuda_runtime.h>
#include <cstdint>

#define Bn   128
#define Tn   50
#define MI   32
#define En   128
#define Dn   144
#define G3   432
#define KD   144
#define KH   72           // GEMM k-slab
#define KP2  76           // padded slab stride (floats)
#define GT   216          // GRU threads (2 gate-rows each)
#define CREG 104          // k-cols per row in registers (52 pairs)
#define TPR  20           // tail pairs per row in smem

typedef unsigned long long ull;

__device__ float g_seq [Bn*Tn*Dn];
__device__ float g_gi  [Bn*Tn*G3];
__device__ float g_hseq[Bn*Tn*Dn];

// ---- f32x2 helpers ---------------------------------------------------------
__device__ __forceinline__ void fma2(ull& d, ull a, ull b) {
    asm("fma.rn.f32x2 %0, %1, %2, %0;" : "+l"(d) : "l"(a), "l"(b));
}
__device__ __forceinline__ void add2(ull& d, ull a) {
    asm("add.rn.f32x2 %0, %0, %1;" : "+l"(d) : "l"(a));
}
__device__ __forceinline__ float hsum2(ull v) {
    float lo, hi;
    asm("mov.b64 {%0,%1}, %2;" : "=f"(lo), "=f"(hi) : "l"(v));
    return lo + hi;
}
__device__ __forceinline__ ull pack2(float lo, float hi) {
    ull v;
    asm("mov.b64 %0, {%1,%2};" : "=l"(v) : "f"(lo), "f"(hi));
    return v;
}
__device__ __forceinline__ void unpack2(float& lo, float& hi, ull v) {
    asm("mov.b64 {%0,%1}, %2;" : "=f"(lo), "=f"(hi) : "l"(v));
}

// ---------------------------------------------------------------------------
__global__ void noop_kernel() {}

// ---------------------------------------------------------------------------
// 1) basket embedding (1 warp does the 128-wide mean pool, float4 gathers)
// ---------------------------------------------------------------------------
__global__ void __launch_bounds__(64)
embed_kernel(const int* __restrict__ x,
             const float* __restrict__ encode_w,
             const float* __restrict__ wchange_w) {
    int bt = blockIdx.x;
    const int* xr = x + (size_t)bt * (MI + 1);
    __shared__ int s_items[MI];
    __shared__ int s_flag;
    int tid = threadIdx.x;
    if (tid < MI) s_items[tid] = xr[tid];
    if (tid == MI) s_flag = xr[MI];
    __syncthreads();

    if (tid < 32) {
        float4 acc = make_float4(0.f, 0.f, 0.f, 0.f);
        int cnt = 0;
        #pragma unroll
        for (int i = 0; i < MI; i++) {
            int it = s_items[i];
            if (it != 0) {
                cnt++;
                float4 v = *(const float4*)(encode_w + (size_t)it * En + 4 * tid);
                acc.x += v.x; acc.y += v.y; acc.z += v.z; acc.w += v.w;
            }
        }
        float inv = 1.f / (float)(cnt > 0 ? cnt : 1);
        acc.x *= inv; acc.y *= inv; acc.z *= inv; acc.w *= inv;
        *(float4*)(g_seq + (size_t)bt * Dn + 4 * tid) = acc;
    } else if (tid < 48) {
        g_seq[(size_t)bt * Dn + En + (tid - 32)] = wchange_w[s_flag * 16 + (tid - 32)];
    }
}

// ---------------------------------------------------------------------------
// 2a) gi GEMM: C[M,432] = A[M,144]*Bm[432,144]^T + bias (64x64, 128 thr)
// ---------------------------------------------------------------------------
__global__ void __launch_bounds__(128)
gemm_tn(const float* __restrict__ A, const float* __restrict__ Bm,
        const float* __restrict__ bias, float* __restrict__ C, int N) {
    extern __shared__ float sm[];
    float* Ast = sm;              // [64][KP2]
    float* Bst = sm + 64 * KP2;   // [64][KP2]

    int tid = threadIdx.x;
    int m0 = blockIdx.y * 64, n0 = blockIdx.x * 64;
    int tx = tid & 15, ty = tid >> 4;

    ull acc[8][4];
    #pragma unroll
    for (int i = 0; i < 8; i++)
        #pragma unroll
        for (int j = 0; j < 4; j++) acc[i][j] = 0ull;

    for (int ks = 0; ks < 2; ks++) {
        int k0 = ks * KH;
        #pragma unroll
        for (int p = 0; p < 9; p++) {
            int idx = tid + p * 128;
            int r = idx / 18, c = idx - 18 * r;
            *(float4*)(Ast + r * KP2 + 4 * c) =
                *(const float4*)(A + (size_t)(m0 + r) * KD + k0 + 4 * c);
        }
        #pragma unroll
        for (int p = 0; p < 9; p++) {
            int idx = tid + p * 128;
            int r = idx / 18, c = idx - 18 * r;
            float4 v = make_float4(0.f, 0.f, 0.f, 0.f);
            if (n0 + r < N)
                v = *(const float4*)(Bm + (size_t)(n0 + r) * KD + k0 + 4 * c);
            *(float4*)(Bst + r * KP2 + 4 * c) = v;
        }
        __syncthreads();

        const float* aBase = Ast + (8 * ty) * KP2;
        const ulonglong2* bP[4];
        #pragma unroll
        for (int j = 0; j < 4; j++)
            bP[j] = (const ulonglong2*)(Bst + (tx + 16 * j) * KP2);

        #pragma unroll 6
        for (int kq = 0; kq < 18; kq++) {
            ulonglong2 b[4];
            #pragma unroll
            for (int j = 0; j < 4; j++) b[j] = bP[j][kq];
            #pragma unroll
            for (int i = 0; i < 8; i++) {
                ulonglong2 a = ((const ulonglong2*)(aBase + i * KP2))[kq];
                #pragma unroll
                for (int j = 0; j < 4; j++) {
                    fma2(acc[i][j], a.x, b[j].x);
                    fma2(acc[i][j], a.y, b[j].y);
                }
            }
        }
        __syncthreads();
    }

    #pragma unroll
    for (int j = 0; j < 4; j++) {
        int n = n0 + tx + 16 * j;
        if (n < N) {
            float bv = bias[n];
            #pragma unroll
            for (int i = 0; i < 8; i++) {
                int m = m0 + 8 * ty + i;
                C[(size_t)m * N + n] = hsum2(acc[i][j]) + bv;
            }
        }
    }
}

// ---------------------------------------------------------------------------
// 2b) fc GEMM: C[M,128] = A[M,144]*Bm[128,144]^T + bias
// ---------------------------------------------------------------------------
__global__ void __launch_bounds__(256)
gemm_fc(const float* __restrict__ A, const float* __restrict__ Bm,
        const float* __restrict__ bias, float* __restrict__ C) {
    extern __shared__ float sm[];
    float* Ast = sm;               // [64][KP2]
    float* Bst = sm + 64 * KP2;    // [128][KP2]

    int tid = threadIdx.x;
    int m0 = blockIdx.x * 64;
    int tx = tid & 15, ty = tid >> 4;

    ull acc[4][8];
    #pragma unroll
    for (int i = 0; i < 4; i++)
        #pragma unroll
        for (int j = 0; j < 8; j++) acc[i][j] = 0ull;

    for (int ks = 0; ks < 2; ks++) {
        int k0 = ks * KH;
        #pragma unroll
        for (int p = 0; p < 5; p++) {
            int idx = tid + p * 256;
            if (idx < 1152) {
                int r = idx / 18, c = idx - 18 * r;
                *(float4*)(Ast + r * KP2 + 4 * c) =
                    *(const float4*)(A + (size_t)(m0 + r) * KD + k0 + 4 * c);
            }
        }
        #pragma unroll
        for (int p = 0; p < 9; p++) {
            int idx = tid + p * 256;
            int r = idx / 18, c = idx - 18 * r;
            *(float4*)(Bst + r * KP2 + 4 * c) =
                *(const float4*)(Bm + (size_t)r * KD + k0 + 4 * c);
        }
        __syncthreads();

        const float* aBase = Ast + (4 * ty) * KP2;
        const ulonglong2* bP[8];
        #pragma unroll
        for (int j = 0; j < 8; j++)
            bP[j] = (const ulonglong2*)(Bst + (tx + 16 * j) * KP2);

        #pragma unroll 6
        for (int kq = 0; kq < 18; kq++) {
            ulonglong2 b[8];
            #pragma unroll
            for (int j = 0; j < 8; j++) b[j] = bP[j][kq];
            #pragma unroll
            for (int i = 0; i < 4; i++) {
                ulonglong2 a = ((const ulonglong2*)(aBase + i * KP2))[kq];
                #pragma unroll
                for (int j = 0; j < 8; j++) {
                    fma2(acc[i][j], a.x, b[j].x);
                    fma2(acc[i][j], a.y, b[j].y);
                }
            }
        }
        __syncthreads();
    }

    #pragma unroll
    for (int j = 0; j < 8; j++) {
        int n = tx + 16 * j;
        float bv = bias[n];
        #pragma unroll
        for (int i = 0; i < 4; i++) {
            int m = m0 + 4 * ty + i;
            C[(size_t)m * En + n] = hsum2(acc[i][j]) + bv;
        }
    }
}

// ---------------------------------------------------------------------------
// 3) GRU: one CTA per batch (grid=128), 216 threads, rows 2j & 2j+1 per
//    thread. k<104 weights in regs; tail in smem, consumed first (pipelined).
//    Epilogue keeps h_prev in a register (no s_h read in epilogue).
// ---------------------------------------------------------------------------
__global__ void __launch_bounds__(GT, 1)
gru_kernel(const float* __restrict__ w_hh, const float* __restrict__ b_hh,
           const float* __restrict__ hidden, float* __restrict__ out) {
    extern __shared__ float sm[];
    ulonglong2* s_wt2 = (ulonglong2*)sm;      // [TPR][216] pair-of-rows
    float* s_h   = sm + TPR * GT * 4;         // [144]
    float* s_A   = s_h + Dn;                  // [432]
    float* s_gin = s_A + G3;                  // [144]

    int b = blockIdx.x;
    int j = threadIdx.x;

    const ull* wr0 = (const ull*)(w_hh + (size_t)(2 * j) * KD);
    const ull* wr1 = wr0 + KD / 2;
    ull wA[CREG / 2], wB[CREG / 2];
    #pragma unroll
    for (int p = 0; p < CREG / 2; p++) wA[p] = wr0[p];
    #pragma unroll
    for (int p = 0; p < CREG / 2; p++) wB[p] = wr1[p];
    #pragma unroll
    for (int p = 0; p < TPR; p++) {
        ulonglong2 v;
        v.x = wr0[CREG / 2 + p];
        v.y = wr1[CREG / 2 + p];
        s_wt2[p * GT + j] = v;
    }

    float bias0, bias1;
    unpack2(bias0, bias1, ((const ull*)b_hh)[j]);

    float h_prev = 0.f;
    if (j < Dn) {
        h_prev = hidden[(size_t)b * Dn + j];
        s_h[j] = h_prev;
    }
    __syncthreads();

    const float* giB = g_gi + (size_t)b * Tn * G3;
    float* hsB       = g_hseq + (size_t)b * Tn * Dn;
    const ulonglong2* h2 = (const ulonglong2*)s_h;   // 36 quads

    ull gicur = ((const ull*)giB)[j];

    for (int t = 0; t < Tn; t++) {
        ull a0 = pack2(bias0, 0.f), a1 = 0ull;        // row 2j
        ull c0 = pack2(bias1, 0.f), c1 = 0ull;        // row 2j+1

        // ---- smem weight tail FIRST (k 104..143), 2-deep pipelined loads ----
        ulonglong2 w0n = s_wt2[0 * GT + j];
        ulonglong2 w1n = s_wt2[1 * GT + j];
        #pragma unroll
        for (int p = 0; p < TPR / 2; p++) {
            ulonglong2 w0 = w0n, w1 = w1n;
            if (p < TPR / 2 - 1) {
                w0n = s_wt2[(2 * p + 2) * GT + j];
                w1n = s_wt2[(2 * p + 3) * GT + j];
            }
            ulonglong2 x = h2[CREG / 4 + p];
            fma2(a0, w0.x, x.x);
            fma2(c0, w0.y, x.x);
            fma2(a1, w1.x, x.y);
            fma2(c1, w1.y, x.y);
        }
        // ---- register-weight section (k 0..103) ----
        #pragma unroll
        for (int q = 0; q < CREG / 4; q++) {
            ulonglong2 x = h2[q];
            fma2(a0, wA[2 * q],     x.x);
            fma2(a1, wA[2 * q + 1], x.y);
            fma2(c0, wB[2 * q],     x.x);
            fma2(c1, wB[2 * q + 1], x.y);
        }
        add2(a0, a1);
        add2(c0, c1);
        float A0 = hsum2(a0);
        float A1 = hsum2(c0);

        float g0, g1;
        unpack2(g0, g1, gicur);
        if (t + 1 < Tn) gicur = ((const ull*)(giB + (t + 1) * G3))[j];

        if (j < Dn) {                              // rows < 288: r or z
            *(float2*)(s_A + 2 * j) = make_float2(g0 + A0, g1 + A1);
        } else {                                   // rows 288..431: n
            *(float2*)(s_A + 2 * j) = make_float2(A0, A1);
            *(float2*)(s_gin + 2 * j - 2 * Dn) = make_float2(g0, g1);
        }
        __syncthreads();

        if (j < Dn) {
            float r = __fdividef(1.f, 1.f + __expf(-s_A[j]));
            float z = __fdividef(1.f, 1.f + __expf(-s_A[j + Dn]));
            float e = __expf(-2.f * (s_gin[j] + r * s_A[j + 2 * Dn]));
            float n = __fdividef(2.f, 1.f + e) - 1.f;   // tanh
            float hn = (1.f - z) * n + z * h_prev;      // h_prev in register
            h_prev = hn;
            s_h[j] = hn;
            hsB[t * Dn + j] = hn;
        }
        __syncthreads();
    }

    if (j < Dn) out[(size_t)Bn * Tn * En + (size_t)b * Dn + j] = h_prev;
}

// ---------------------------------------------------------------------------
extern "C" void kernel_launch(void* const* d_in, const int* in_sizes, int n_in,
                              void* d_out, int out_size) {
    const int*   x        = (const int*)  d_in[0];
    const float* hidden   = (const float*)d_in[2];
    const float* encode_w = (const float*)d_in[3];
    const float* wchange  = (const float*)d_in[4];
    const float* w_ih     = (const float*)d_in[5];
    const float* w_hh     = (const float*)d_in[6];
    const float* b_ih     = (const float*)d_in[7];
    const float* b_hh     = (const float*)d_in[8];
    const float* fc_w     = (const float*)d_in[9];
    const float* fc_b     = (const float*)d_in[10];
    float* out = (float*)d_out;

    float *p_seq, *p_gi, *p_hseq;
    cudaGetSymbolAddress((void**)&p_seq,  g_seq);
    cudaGetSymbolAddress((void**)&p_gi,   g_gi);
    cudaGetSymbolAddress((void**)&p_hseq, g_hseq);

    const int gemm_smem = 2 * 64 * KP2 * 4;                   // 38912 B
    const int fc_smem   = (64 + 128) * KP2 * 4;               // 58368 B
    const int gru_smem  = (TPR * GT * 4 + Dn + G3 + Dn) * 4;  // 71904 B
    cudaFuncSetAttribute(gru_kernel, cudaFuncAttributeMaxDynamicSharedMemorySize, gru_smem);
    cudaFuncSetAttribute(gemm_fc,    cudaFuncAttributeMaxDynamicSharedMemorySize, fc_smem);

    // 1) embed
    embed_kernel<<<Bn * Tn, 64>>>(x, encode_w, wchange);

    // spacers so the ncu capture slot (launch #4) lands on the gi GEMM
    noop_kernel<<<1, 32>>>();
    noop_kernel<<<1, 32>>>();

    // 2) gi = seq @ w_ih^T + b_ih   (6400 x 432)
    {
        dim3 grid((G3 + 63) / 64, (Bn * Tn) / 64);
        gemm_tn<<<grid, 128, gemm_smem>>>(p_seq, w_ih, b_ih, p_gi, G3);
    }

    // 3) GRU recurrence (one CTA per batch row, grid=128)
    gru_kernel<<<Bn, GT, gru_smem>>>(w_hh, b_hh, hidden, out);

    // 4) dynamic_user = hseq @ fc_w^T + fc_b  (6400 x 128) -> out head
    gemm_fc<<<(Bn * Tn) / 64, 256, fc_smem>>>(p_hseq, fc_w, fc_b, out);
}